// round 2
// baseline (speedup 1.0000x reference)
#include <cuda_runtime.h>
#include <math.h>
#include <stdint.h>

#define FIN 256
#define HID2 128   // 2*H (conv1 output width)
#define HH  64     // H
#define NMAX 50000
#define EMAX 800000
#define ENMAX (EMAX + NMAX)

// ---------------- scratch (static device globals; no allocations) -------------
__device__ __align__(16) float g_h1  [NMAX * HID2];
__device__ __align__(16) float g_out1[NMAX * HID2];
__device__ __align__(16) float g_h2  [NMAX * HH];
__device__ __align__(16) float g_out2[NMAX * HH];
__device__ float g_asrc1[NMAX * 2], g_adst1[NMAX * 2];
__device__ unsigned g_emax1[NMAX * 2];
__device__ float g_denom1[NMAX * 2];
__device__ float g_asrc2[NMAX], g_adst2[NMAX];
__device__ unsigned g_emax2[NMAX];
__device__ float g_denom2[NMAX];
__device__ __align__(16) float g_e1[ENMAX * 2];  // per-edge logits / numerators, conv1
__device__ float g_e2[ENMAX];                    // per-edge logits / numerators, conv2
__device__ float g_sum[FIN], g_sumsq[FIN];
__device__ float g_scale[FIN], g_shift[FIN];
__device__ __align__(16) float g_W1p[FIN * HID2];
__device__ float g_c1[HID2];
__device__ float g_zero[HID2];   // stays zero (zero-initialized, never written)

// ---------------- helpers ----------------------------------------------------
__device__ __forceinline__ float lrelu(float x) { return x > 0.f ? x : 0.2f * x; }
__device__ __forceinline__ float eluf(float x)  { return x > 0.f ? x : expm1f(x); }

// monotonic float->uint key so atomicMax(unsigned) == float max
__device__ __forceinline__ unsigned fkey(float f) {
    unsigned b = __float_as_uint(f);
    return (b & 0x80000000u) ? ~b : (b | 0x80000000u);
}
__device__ __forceinline__ float funkey(unsigned k) {
    return __uint_as_float((k & 0x80000000u) ? (k ^ 0x80000000u) : ~k);
}

__device__ __forceinline__ void redAdd4(float* p, float4 v) {
    asm volatile("red.global.add.v4.f32 [%0], {%1,%2,%3,%4};"
                 :: "l"(p), "f"(v.x), "f"(v.y), "f"(v.z), "f"(v.w) : "memory");
}
__device__ __forceinline__ void redAdd2(float* p, float2 v) {
    asm volatile("red.global.add.v2.f32 [%0], {%1,%2};"
                 :: "l"(p), "f"(v.x), "f"(v.y) : "memory");
}

// ---------------- init (zero accumulators every call) -------------------------
__global__ void init_kernel(int Nn) {
    int i = blockIdx.x * blockDim.x + threadIdx.x;
    if (i < Nn * HID2) g_out1[i] = 0.f;
    if (i < Nn * HH)   g_out2[i] = 0.f;
    if (i < Nn * 2) { g_denom1[i] = 0.f; g_emax1[i] = 0u; }
    if (i < Nn)     { g_denom2[i] = 0.f; g_emax2[i] = 0u; }
    if (i < FIN)    { g_sum[i] = 0.f; g_sumsq[i] = 0.f; }
}

// ---------------- batchnorm stats ---------------------------------------------
__global__ void stats_kernel(const float* __restrict__ x, int Nn, int rowsPerBlock) {
    int col = threadIdx.x;                 // 256 threads = 256 features
    int r0 = blockIdx.x * rowsPerBlock;
    int r1 = min(r0 + rowsPerBlock, Nn);
    float s = 0.f, s2 = 0.f;
    for (int r = r0; r < r1; r++) {
        float v = x[(size_t)r * FIN + col];
        s += v; s2 += v * v;
    }
    atomicAdd(&g_sum[col], s);
    atomicAdd(&g_sumsq[col], s2);
}

__global__ void prep_scale(const float* __restrict__ gamma,
                           const float* __restrict__ beta, int Nn) {
    int f = threadIdx.x;
    float inv = 1.f / (float)Nn;
    float mu  = g_sum[f] * inv;
    float var = g_sumsq[f] * inv - mu * mu;
    float rs  = rsqrtf(var + 1e-5f);
    float sc  = rs * gamma[f];
    g_scale[f] = sc;
    g_shift[f] = beta[f] - mu * sc;
}

__global__ void prep_w1(const float* __restrict__ W1) {
    int i = blockIdx.x * blockDim.x + threadIdx.x;
    if (i < FIN * HID2) g_W1p[i] = g_scale[i / HID2] * W1[i];
}

__global__ void prep_c1(const float* __restrict__ W1) {
    int k = threadIdx.x;  // 128
    float s = 0.f;
    for (int f = 0; f < FIN; f++) s += g_shift[f] * W1[f * HID2 + k];
    g_c1[k] = s;
}

// ---------------- tiled SGEMM: C[M,N] = act(A[M,K]) @ B[K,N] + cbias ----------
// ELU_IN: A-element transform elu(a + abias[kcol]) (fused conv1-output activation)
template <int BM, int BN, int BK, int TM, int TN, bool ELU_IN>
__global__ void __launch_bounds__(256)
sgemm_kernel(int M, int N, int K,
             const float* __restrict__ A, const float* __restrict__ B,
             const float* __restrict__ abias, const float* __restrict__ cbias,
             float* __restrict__ C) {
    __shared__ float As[BK][BM + 4];
    __shared__ float Bs[BK][BN];
    const int tid = threadIdx.x;
    const int row0 = blockIdx.x * BM;
    constexpr int TCOLS = BN / TN;
    const int tcol = (tid % TCOLS) * TN;
    const int trow = (tid / TCOLS) * TM;

    float acc[TM][TN];
#pragma unroll
    for (int i = 0; i < TM; i++)
#pragma unroll
        for (int j = 0; j < TN; j++) acc[i][j] = 0.f;

    for (int k0 = 0; k0 < K; k0 += BK) {
        // load A tile (BM x BK), float4 along K, store transposed
#pragma unroll 2
        for (int i = tid; i < BM * BK / 4; i += 256) {
            int r  = i / (BK / 4);
            int c4 = (i % (BK / 4)) * 4;
            int gr = row0 + r;
            float4 v = make_float4(0.f, 0.f, 0.f, 0.f);
            if (gr < M) v = *(const float4*)(A + (size_t)gr * K + k0 + c4);
            if (ELU_IN) {
                v.x = eluf(v.x + abias[k0 + c4 + 0]);
                v.y = eluf(v.y + abias[k0 + c4 + 1]);
                v.z = eluf(v.z + abias[k0 + c4 + 2]);
                v.w = eluf(v.w + abias[k0 + c4 + 3]);
            }
            As[c4 + 0][r] = v.x; As[c4 + 1][r] = v.y;
            As[c4 + 2][r] = v.z; As[c4 + 3][r] = v.w;
        }
        // load B tile (BK x BN)
#pragma unroll 2
        for (int i = tid; i < BK * BN / 4; i += 256) {
            int r  = i / (BN / 4);
            int c4 = (i % (BN / 4)) * 4;
            *(float4*)&Bs[r][c4] = *(const float4*)(B + (size_t)(k0 + r) * N + c4);
        }
        __syncthreads();

#pragma unroll
        for (int k = 0; k < BK; k++) {
            float ra[TM], rb[TN];
#pragma unroll
            for (int i = 0; i < TM; i++) ra[i] = As[k][trow + i];
#pragma unroll
            for (int j = 0; j < TN; j++) rb[j] = Bs[k][tcol + j];
#pragma unroll
            for (int i = 0; i < TM; i++)
#pragma unroll
                for (int j = 0; j < TN; j++) acc[i][j] += ra[i] * rb[j];
        }
        __syncthreads();
    }

#pragma unroll
    for (int i = 0; i < TM; i++) {
        int gr = row0 + trow + i;
        if (gr >= M) continue;
#pragma unroll
        for (int j = 0; j < TN; j += 4) {
            float4 v;
            v.x = acc[i][j + 0] + cbias[tcol + j + 0];
            v.y = acc[i][j + 1] + cbias[tcol + j + 1];
            v.z = acc[i][j + 2] + cbias[tcol + j + 2];
            v.w = acc[i][j + 3] + cbias[tcol + j + 3];
            *(float4*)(C + (size_t)gr * N + tcol + j) = v;
        }
    }
}

// ---------------- attention coefficients (warp per node) ----------------------
__global__ void att1_kernel(const float* __restrict__ a_src,
                            const float* __restrict__ a_dst, int Nn) {
    int gw   = (blockIdx.x * blockDim.x + threadIdx.x) >> 5;
    int lane = threadIdx.x & 31;
    if (gw >= Nn) return;
    const float* row = g_h1 + (size_t)gw * HID2;
    float h0a = row[lane], h0b = row[lane + 32];
    float h1a = row[64 + lane], h1b = row[96 + lane];
    float s0 = h0a * a_src[lane] + h0b * a_src[lane + 32];
    float d0 = h0a * a_dst[lane] + h0b * a_dst[lane + 32];
    float s1 = h1a * a_src[64 + lane] + h1b * a_src[96 + lane];
    float d1 = h1a * a_dst[64 + lane] + h1b * a_dst[96 + lane];
#pragma unroll
    for (int o = 16; o; o >>= 1) {
        s0 += __shfl_down_sync(0xffffffffu, s0, o);
        d0 += __shfl_down_sync(0xffffffffu, d0, o);
        s1 += __shfl_down_sync(0xffffffffu, s1, o);
        d1 += __shfl_down_sync(0xffffffffu, d1, o);
    }
    if (lane == 0) {
        g_asrc1[gw * 2] = s0; g_asrc1[gw * 2 + 1] = s1;
        g_adst1[gw * 2] = d0; g_adst1[gw * 2 + 1] = d1;
    }
}

__global__ void att2_kernel(const float* __restrict__ a_src,
                            const float* __restrict__ a_dst, int Nn) {
    int gw   = (blockIdx.x * blockDim.x + threadIdx.x) >> 5;
    int lane = threadIdx.x & 31;
    if (gw >= Nn) return;
    const float* row = g_h2 + (size_t)gw * HH;
    float ha = row[lane], hb = row[lane + 32];
    float s = ha * a_src[lane] + hb * a_src[lane + 32];
    float d = ha * a_dst[lane] + hb * a_dst[lane + 32];
#pragma unroll
    for (int o = 16; o; o >>= 1) {
        s += __shfl_down_sync(0xffffffffu, s, o);
        d += __shfl_down_sync(0xffffffffu, d, o);
    }
    if (lane == 0) { g_asrc2[gw] = s; g_adst2[gw] = d; }
}

// ---------------- conv1 edge passes -------------------------------------------
// pass 1: compute logits e (random gathers), cache them, atomicMax per dst
__global__ void edge_max1(const int* __restrict__ ei, int E, int Nn) {
    int i = blockIdx.x * blockDim.x + threadIdx.x;
    if (i >= E + Nn) return;
    int src = i < E ? ei[i] : i - E;
    int dst = i < E ? ei[E + i] : i - E;
    float2 as = *(const float2*)&g_asrc1[src * 2];
    float2 ad = *(const float2*)&g_adst1[dst * 2];
    float e0 = lrelu(as.x + ad.x);
    float e1 = lrelu(as.y + ad.y);
    *(float2*)&g_e1[i * 2] = make_float2(e0, e1);
    atomicMax(&g_emax1[dst * 2 + 0], fkey(e0));
    atomicMax(&g_emax1[dst * 2 + 1], fkey(e1));
}

// pass 2: read cached logits, gather emax[dst], cache exp numerators, sum denom
__global__ void edge_denom1(const int* __restrict__ ei, int E, int Nn) {
    int i = blockIdx.x * blockDim.x + threadIdx.x;
    if (i >= E + Nn) return;
    int dst = i < E ? ei[E + i] : i - E;
    float2 e = *(const float2*)&g_e1[i * 2];
    float ee0 = expf(e.x - funkey(g_emax1[dst * 2 + 0]));
    float ee1 = expf(e.y - funkey(g_emax1[dst * 2 + 1]));
    *(float2*)&g_e1[i * 2] = make_float2(ee0, ee1);
    atomicAdd(&g_denom1[dst * 2 + 0], ee0);
    atomicAdd(&g_denom1[dst * 2 + 1], ee1);
}

// pass 3: warp per edge; alpha = cached ee / denom[dst]; scatter h1[src]*alpha
__global__ void edge_scatter1(const int* __restrict__ ei, int E, int Nn) {
    int warp = (blockIdx.x * blockDim.x + threadIdx.x) >> 5;
    int lane = threadIdx.x & 31;
    if (warp >= E + Nn) return;
    int src = warp < E ? ei[warp] : warp - E;
    int dst = warp < E ? ei[E + warp] : warp - E;
    float a = 0.f;
    if (lane < 2) a = g_e1[warp * 2 + lane] / g_denom1[dst * 2 + lane];
    float a0 = __shfl_sync(0xffffffffu, a, 0);
    float a1 = __shfl_sync(0xffffffffu, a, 1);
    float al = (lane < 16) ? a0 : a1;
    float4 v = *(const float4*)(g_h1 + (size_t)src * HID2 + lane * 4);
    v.x *= al; v.y *= al; v.z *= al; v.w *= al;
    redAdd4(g_out1 + (size_t)dst * HID2 + lane * 4, v);
}

// ---------------- conv2 edge passes -------------------------------------------
__global__ void edge_max2(const int* __restrict__ ei, int E, int Nn) {
    int i = blockIdx.x * blockDim.x + threadIdx.x;
    if (i >= E + Nn) return;
    int src = i < E ? ei[i] : i - E;
    int dst = i < E ? ei[E + i] : i - E;
    float e = lrelu(g_asrc2[src] + g_adst2[dst]);
    g_e2[i] = e;
    atomicMax(&g_emax2[dst], fkey(e));
}

__global__ void edge_denom2(const int* __restrict__ ei, int E, int Nn) {
    int i = blockIdx.x * blockDim.x + threadIdx.x;
    if (i >= E + Nn) return;
    int dst = i < E ? ei[E + i] : i - E;
    float ee = expf(g_e2[i] - funkey(g_emax2[dst]));
    g_e2[i] = ee;
    atomicAdd(&g_denom2[dst], ee);
}

__global__ void edge_scatter2(const int* __restrict__ ei, int E, int Nn) {
    int warp = (blockIdx.x * blockDim.x + threadIdx.x) >> 5;
    int lane = threadIdx.x & 31;
    if (warp >= E + Nn) return;
    int src = warp < E ? ei[warp] : warp - E;
    int dst = warp < E ? ei[E + warp] : warp - E;
    float a = 0.f;
    if (lane == 0) a = g_e2[warp] / g_denom2[dst];
    float al = __shfl_sync(0xffffffffu, a, 0);
    float2 v = *(const float2*)(g_h2 + (size_t)src * HH + lane * 2);
    v.x *= al; v.y *= al;
    redAdd2(g_out2 + (size_t)dst * HH + lane * 2, v);
}

// ---------------- final MLP ----------------------------------------------------
__global__ void final_kernel(const float* __restrict__ b2,
                             const float* __restrict__ Wc1,
                             const float* __restrict__ bc1,
                             const float* __restrict__ Wc2,
                             const float* __restrict__ bc2,
                             float* __restrict__ out, int Nn) {
    __shared__ float sW1[64 * 16], sW2[32], sb1[16], sb2[2], sB2[64];
    int tid = threadIdx.x;
    for (int i = tid; i < 64 * 16; i += blockDim.x) sW1[i] = Wc1[i];
    if (tid < 32) sW2[tid] = Wc2[tid];
    if (tid < 16) sb1[tid] = bc1[tid];
    if (tid < 2)  sb2[tid] = bc2[tid];
    if (tid < 64) sB2[tid] = b2[tid];
    __syncthreads();
    int n = blockIdx.x * blockDim.x + tid;
    if (n >= Nn) return;
    const float* row = g_out2 + (size_t)n * HH;
    float t[16];
#pragma unroll
    for (int j = 0; j < 16; j++) t[j] = sb1[j];
#pragma unroll 8
    for (int i = 0; i < 64; i++) {
        float v = row[i] + sB2[i];
#pragma unroll
        for (int j = 0; j < 16; j++) t[j] += v * sW1[i * 16 + j];
    }
    float o0 = sb2[0], o1 = sb2[1];
#pragma unroll
    for (int j = 0; j < 16; j++) {
        float tj = t[j] > 0.f ? t[j] : 0.f;
        o0 += tj * sW2[j * 2]; o1 += tj * sW2[j * 2 + 1];
    }
    out[n * 2]     = o0;
    out[n * 2 + 1] = o1;
}

// ---------------- launch --------------------------------------------------------
extern "C" void kernel_launch(void* const* d_in, const int* in_sizes, int n_in,
                              void* d_out, int out_size) {
    const float* x  = (const float*)d_in[0];
    const int*   ei = (const int*)d_in[1];
    int Nn = in_sizes[0] / FIN;
    int E  = in_sizes[1] / 2;

    // locate weight block robustly: gamma(256), beta(256), W1(32768), ...
    int g = -1;
    for (int i = 2; i + 2 < n_in; i++) {
        if (in_sizes[i] == 256 && in_sizes[i + 1] == 256 && in_sizes[i + 2] == FIN * HID2) {
            g = i; break;
        }
    }
    if (g < 0) g = 6;  // fallback to nominal layout
    const float* gamma  = (const float*)d_in[g + 0];
    const float* beta   = (const float*)d_in[g + 1];
    const float* W1     = (const float*)d_in[g + 2];
    const float* a_src1 = (const float*)d_in[g + 3];
    const float* a_dst1 = (const float*)d_in[g + 4];
    const float* b1     = (const float*)d_in[g + 5];
    const float* W2     = (const float*)d_in[g + 6];
    const float* a_src2 = (const float*)d_in[g + 7];
    const float* a_dst2 = (const float*)d_in[g + 8];
    const float* b2     = (const float*)d_in[g + 9];
    const float* Wc1    = (const float*)d_in[g + 10];
    const float* bc1    = (const float*)d_in[g + 11];
    const float* Wc2    = (const float*)d_in[g + 12];
    const float* bc2    = (const float*)d_in[g + 13];
    float* out = (float*)d_out;

    float *p_h1, *p_out1, *p_h2, *p_W1p, *p_c1, *p_zero;
    cudaGetSymbolAddress((void**)&p_h1,   g_h1);
    cudaGetSymbolAddress((void**)&p_out1, g_out1);
    cudaGetSymbolAddress((void**)&p_h2,   g_h2);
    cudaGetSymbolAddress((void**)&p_W1p,  g_W1p);
    cudaGetSymbolAddress((void**)&p_c1,   g_c1);
    cudaGetSymbolAddress((void**)&p_zero, g_zero);

    int EN = E + Nn;

    // 1) zero accumulators
    init_kernel<<<(Nn * HID2 + 255) / 256, 256>>>(Nn);

    // 2) batchnorm stats + folded weights
    int rowsPerBlock = 256;
    stats_kernel<<<(Nn + rowsPerBlock - 1) / rowsPerBlock, 256>>>(x, Nn, rowsPerBlock);
    prep_scale<<<1, 256>>>(gamma, beta, Nn);
    prep_w1<<<(FIN * HID2 + 255) / 256, 256>>>(W1);
    prep_c1<<<1, HID2>>>(W1);

    // 3) GEMM1: h1 = xn @ W1  (BN folded)
    sgemm_kernel<128, 128, 16, 8, 8, false>
        <<<(Nn + 127) / 128, 256>>>(Nn, HID2, FIN, x, p_W1p, nullptr, p_c1, p_h1);

    // 4) conv1 attention + softmax aggregation
    att1_kernel<<<(Nn * 32 + 255) / 256, 256>>>(a_src1, a_dst1, Nn);
    edge_max1   <<<(EN + 255) / 256, 256>>>(ei, E, Nn);
    edge_denom1 <<<(EN + 255) / 256, 256>>>(ei, E, Nn);
    edge_scatter1<<<((size_t)EN * 32 + 255) / 256, 256>>>(ei, E, Nn);

    // 5) GEMM2: h2 = elu(out1 + b1) @ W2   (activation fused into A load)
    sgemm_kernel<128, 64, 16, 8, 4, true>
        <<<(Nn + 127) / 128, 256>>>(Nn, HH, HID2, p_out1, W2, b1, p_zero, p_h2);

    // 6) conv2 attention + softmax aggregation
    att2_kernel<<<(Nn * 32 + 255) / 256, 256>>>(a_src2, a_dst2, Nn);
    edge_max2   <<<(EN + 255) / 256, 256>>>(ei, E, Nn);
    edge_denom2 <<<(EN + 255) / 256, 256>>>(ei, E, Nn);
    edge_scatter2<<<((size_t)EN * 32 + 255) / 256, 256>>>(ei, E, Nn);

    // 7) final MLP: out = relu((out2+b2) @ Wc1 + bc1) @ Wc2 + bc2
    final_kernel<<<(Nn + 255) / 256, 256>>>(b2, Wc1, bc1, Wc2, bc2, out, Nn);
}

// round 3
// speedup vs baseline: 1.0603x; 1.0603x over previous
#include <cuda_runtime.h>
#include <math.h>
#include <stdint.h>

#define FIN 256
#define HID2 128   // 2*H (conv1 output width)
#define HH  64     // H
#define NMAX 50000

// ---------------- scratch (static device globals; no allocations) -------------
__device__ __align__(16) float g_h1  [NMAX * HID2];
__device__ __align__(16) float g_out1[NMAX * HID2];   // UNNORMALIZED conv1 sums
__device__ __align__(16) float g_h2  [NMAX * HH];
__device__ __align__(16) float g_out2[NMAX * HH];     // UNNORMALIZED conv2 sums
__device__ float g_asrc1[NMAX * 2], g_adst1[NMAX * 2];
__device__ __align__(8) float g_denom1[NMAX * 2];
__device__ float g_asrc2[NMAX], g_adst2[NMAX];
__device__ float g_denom2[NMAX];
__device__ float g_sum[FIN], g_sumsq[FIN];
__device__ float g_scale[FIN], g_shift[FIN];
__device__ __align__(16) float g_W1p[FIN * HID2];
__device__ float g_c1[HID2];
__device__ float g_zero[HID2];   // stays zero (zero-initialized, never written)

// ---------------- helpers ----------------------------------------------------
__device__ __forceinline__ float lrelu(float x) { return x > 0.f ? x : 0.2f * x; }
__device__ __forceinline__ float eluf(float x)  { return x > 0.f ? x : expm1f(x); }

__device__ __forceinline__ void redAdd4(float* p, float4 v) {
    asm volatile("red.global.add.v4.f32 [%0], {%1,%2,%3,%4};"
                 :: "l"(p), "f"(v.x), "f"(v.y), "f"(v.z), "f"(v.w) : "memory");
}
__device__ __forceinline__ void redAdd2(float* p, float2 v) {
    asm volatile("red.global.add.v2.f32 [%0], {%1,%2};"
                 :: "l"(p), "f"(v.x), "f"(v.y) : "memory");
}

// ---------------- init (zero accumulators every call) -------------------------
__global__ void init_kernel(int Nn) {
    int i = blockIdx.x * blockDim.x + threadIdx.x;
    if (i < Nn * HID2) g_out1[i] = 0.f;
    if (i < Nn * HH)   g_out2[i] = 0.f;
    if (i < Nn * 2)    g_denom1[i] = 0.f;
    if (i < Nn)        g_denom2[i] = 0.f;
    if (i < FIN)     { g_sum[i] = 0.f; g_sumsq[i] = 0.f; }
}

// ---------------- batchnorm stats ---------------------------------------------
__global__ void stats_kernel(const float* __restrict__ x, int Nn, int rowsPerBlock) {
    int col = threadIdx.x;                 // 256 threads = 256 features
    int r0 = blockIdx.x * rowsPerBlock;
    int r1 = min(r0 + rowsPerBlock, Nn);
    float s = 0.f, s2 = 0.f;
    for (int r = r0; r < r1; r++) {
        float v = x[(size_t)r * FIN + col];
        s += v; s2 += v * v;
    }
    atomicAdd(&g_sum[col], s);
    atomicAdd(&g_sumsq[col], s2);
}

__global__ void prep_scale(const float* __restrict__ gamma,
                           const float* __restrict__ beta, int Nn) {
    int f = threadIdx.x;
    float inv = 1.f / (float)Nn;
    float mu  = g_sum[f] * inv;
    float var = g_sumsq[f] * inv - mu * mu;
    float rs  = rsqrtf(var + 1e-5f);
    float sc  = rs * gamma[f];
    g_scale[f] = sc;
    g_shift[f] = beta[f] - mu * sc;
}

__global__ void prep_w1(const float* __restrict__ W1) {
    int i = blockIdx.x * blockDim.x + threadIdx.x;
    if (i < FIN * HID2) g_W1p[i] = g_scale[i / HID2] * W1[i];
}

__global__ void prep_c1(const float* __restrict__ W1) {
    int k = threadIdx.x;  // 128
    float s = 0.f;
    for (int f = 0; f < FIN; f++) s += g_shift[f] * W1[f * HID2 + k];
    g_c1[k] = s;
}

// ---------------- tiled SGEMM: C[M,N] = act(A[M,K]) @ B[K,N] + cbias ----------
// NORM_ELU: A-element transform elu(a / denom[row, head(kcol)] + abias[kcol])
//           (fuses conv1 softmax normalization + bias + ELU into the A load)
template <int BM, int BN, int BK, int TM, int TN, bool NORM_ELU>
__global__ void __launch_bounds__(256)
sgemm_kernel(int M, int N, int K,
             const float* __restrict__ A, const float* __restrict__ B,
             const float* __restrict__ denom, const float* __restrict__ abias,
             const float* __restrict__ cbias, float* __restrict__ C) {
    __shared__ float As[BK][BM + 4];
    __shared__ float Bs[BK][BN];
    const int tid = threadIdx.x;
    const int row0 = blockIdx.x * BM;
    constexpr int TCOLS = BN / TN;
    const int tcol = (tid % TCOLS) * TN;
    const int trow = (tid / TCOLS) * TM;

    float acc[TM][TN];
#pragma unroll
    for (int i = 0; i < TM; i++)
#pragma unroll
        for (int j = 0; j < TN; j++) acc[i][j] = 0.f;

    for (int k0 = 0; k0 < K; k0 += BK) {
        // load A tile (BM x BK), float4 along K, store transposed
#pragma unroll 2
        for (int i = tid; i < BM * BK / 4; i += 256) {
            int r  = i / (BK / 4);
            int c4 = (i % (BK / 4)) * 4;
            int gr = row0 + r;
            float4 v = make_float4(0.f, 0.f, 0.f, 0.f);
            if (gr < M) {
                v = *(const float4*)(A + (size_t)gr * K + k0 + c4);
                if (NORM_ELU) {
                    // head = (k0+c4) / 64 ; all 4 lanes same head (c4 % 4 == 0, 64 % 4 == 0)
                    float d = denom[gr * 2 + ((k0 + c4) >> 6)];
                    float rd = 1.f / d;
                    v.x = eluf(v.x * rd + abias[k0 + c4 + 0]);
                    v.y = eluf(v.y * rd + abias[k0 + c4 + 1]);
                    v.z = eluf(v.z * rd + abias[k0 + c4 + 2]);
                    v.w = eluf(v.w * rd + abias[k0 + c4 + 3]);
                }
            }
            As[c4 + 0][r] = v.x; As[c4 + 1][r] = v.y;
            As[c4 + 2][r] = v.z; As[c4 + 3][r] = v.w;
        }
        // load B tile (BK x BN)
#pragma unroll 2
        for (int i = tid; i < BK * BN / 4; i += 256) {
            int r  = i / (BN / 4);
            int c4 = (i % (BN / 4)) * 4;
            *(float4*)&Bs[r][c4] = *(const float4*)(B + (size_t)(k0 + r) * N + c4);
        }
        __syncthreads();

#pragma unroll
        for (int k = 0; k < BK; k++) {
            float ra[TM], rb[TN];
#pragma unroll
            for (int i = 0; i < TM; i++) ra[i] = As[k][trow + i];
#pragma unroll
            for (int j = 0; j < TN; j++) rb[j] = Bs[k][tcol + j];
#pragma unroll
            for (int i = 0; i < TM; i++)
#pragma unroll
                for (int j = 0; j < TN; j++) acc[i][j] += ra[i] * rb[j];
        }
        __syncthreads();
    }

#pragma unroll
    for (int i = 0; i < TM; i++) {
        int gr = row0 + trow + i;
        if (gr >= M) continue;
#pragma unroll
        for (int j = 0; j < TN; j += 4) {
            float4 v;
            v.x = acc[i][j + 0] + cbias[tcol + j + 0];
            v.y = acc[i][j + 1] + cbias[tcol + j + 1];
            v.z = acc[i][j + 2] + cbias[tcol + j + 2];
            v.w = acc[i][j + 3] + cbias[tcol + j + 3];
            *(float4*)(C + (size_t)gr * N + tcol + j) = v;
        }
    }
}

// ---------------- attention coefficients (warp per node) ----------------------
__global__ void att1_kernel(const float* __restrict__ a_src,
                            const float* __restrict__ a_dst, int Nn) {
    int gw   = (blockIdx.x * blockDim.x + threadIdx.x) >> 5;
    int lane = threadIdx.x & 31;
    if (gw >= Nn) return;
    const float* row = g_h1 + (size_t)gw * HID2;
    float h0a = row[lane], h0b = row[lane + 32];
    float h1a = row[64 + lane], h1b = row[96 + lane];
    float s0 = h0a * a_src[lane] + h0b * a_src[lane + 32];
    float d0 = h0a * a_dst[lane] + h0b * a_dst[lane + 32];
    float s1 = h1a * a_src[64 + lane] + h1b * a_src[96 + lane];
    float d1 = h1a * a_dst[64 + lane] + h1b * a_dst[96 + lane];
#pragma unroll
    for (int o = 16; o; o >>= 1) {
        s0 += __shfl_down_sync(0xffffffffu, s0, o);
        d0 += __shfl_down_sync(0xffffffffu, d0, o);
        s1 += __shfl_down_sync(0xffffffffu, s1, o);
        d1 += __shfl_down_sync(0xffffffffu, d1, o);
    }
    if (lane == 0) {
        g_asrc1[gw * 2] = s0; g_asrc1[gw * 2 + 1] = s1;
        g_adst1[gw * 2] = d0; g_adst1[gw * 2 + 1] = d1;
    }
}

__global__ void att2_kernel(const float* __restrict__ a_src,
                            const float* __restrict__ a_dst, int Nn) {
    int gw   = (blockIdx.x * blockDim.x + threadIdx.x) >> 5;
    int lane = threadIdx.x & 31;
    if (gw >= Nn) return;
    const float* row = g_h2 + (size_t)gw * HH;
    float ha = row[lane], hb = row[lane + 32];
    float s = ha * a_src[lane] + hb * a_src[lane + 32];
    float d = ha * a_dst[lane] + hb * a_dst[lane + 32];
#pragma unroll
    for (int o = 16; o; o >>= 1) {
        s += __shfl_down_sync(0xffffffffu, s, o);
        d += __shfl_down_sync(0xffffffffu, d, o);
    }
    if (lane == 0) { g_asrc2[gw] = s; g_adst2[gw] = d; }
}

// ---------------- conv1 fused edge pass ----------------------------------------
// warp per edge: ee = exp(lrelu(asrc[src]+adst[dst])); atomically accumulate
// denom[dst] and ee * h1[src] into out1[dst]. Normalization deferred to GEMM2.
__global__ void edge_fused1(const int* __restrict__ ei, int E, int Nn) {
    int warp = (blockIdx.x * blockDim.x + threadIdx.x) >> 5;
    int lane = threadIdx.x & 31;
    if (warp >= E + Nn) return;
    int src = warp < E ? ei[warp] : warp - E;
    int dst = warp < E ? ei[E + warp] : warp - E;
    float ee = 0.f;
    if (lane < 2) {
        float e = lrelu(g_asrc1[src * 2 + lane] + g_adst1[dst * 2 + lane]);
        ee = __expf(e);
        atomicAdd(&g_denom1[dst * 2 + lane], ee);
    }
    float a0 = __shfl_sync(0xffffffffu, ee, 0);
    float a1 = __shfl_sync(0xffffffffu, ee, 1);
    float al = (lane < 16) ? a0 : a1;   // lanes 0-15 -> head0 cols, 16-31 -> head1
    float4 v = *(const float4*)(g_h1 + (size_t)src * HID2 + lane * 4);
    v.x *= al; v.y *= al; v.z *= al; v.w *= al;
    redAdd4(g_out1 + (size_t)dst * HID2 + lane * 4, v);
}

// ---------------- conv2 fused edge pass ----------------------------------------
__global__ void edge_fused2(const int* __restrict__ ei, int E, int Nn) {
    int warp = (blockIdx.x * blockDim.x + threadIdx.x) >> 5;
    int lane = threadIdx.x & 31;
    if (warp >= E + Nn) return;
    int src = warp < E ? ei[warp] : warp - E;
    int dst = warp < E ? ei[E + warp] : warp - E;
    float ee = 0.f;
    if (lane == 0) {
        float e = lrelu(g_asrc2[src] + g_adst2[dst]);
        ee = __expf(e);
        atomicAdd(&g_denom2[dst], ee);
    }
    float al = __shfl_sync(0xffffffffu, ee, 0);
    float2 v = *(const float2*)(g_h2 + (size_t)src * HH + lane * 2);
    v.x *= al; v.y *= al;
    redAdd2(g_out2 + (size_t)dst * HH + lane * 2, v);
}

// ---------------- final MLP (conv2 normalization fused in) ----------------------
__global__ void final_kernel(const float* __restrict__ b2,
                             const float* __restrict__ Wc1,
                             const float* __restrict__ bc1,
                             const float* __restrict__ Wc2,
                             const float* __restrict__ bc2,
                             float* __restrict__ out, int Nn) {
    __shared__ float sW1[64 * 16], sW2[32], sb1[16], sb2[2], sB2[64];
    int tid = threadIdx.x;
    for (int i = tid; i < 64 * 16; i += blockDim.x) sW1[i] = Wc1[i];
    if (tid < 32) sW2[tid] = Wc2[tid];
    if (tid < 16) sb1[tid] = bc1[tid];
    if (tid < 2)  sb2[tid] = bc2[tid];
    if (tid < 64) sB2[tid] = b2[tid];
    __syncthreads();
    int n = blockIdx.x * blockDim.x + tid;
    if (n >= Nn) return;
    const float* row = g_out2 + (size_t)n * HH;
    float rd = 1.f / g_denom2[n];
    float t[16];
#pragma unroll
    for (int j = 0; j < 16; j++) t[j] = sb1[j];
#pragma unroll 8
    for (int i = 0; i < 64; i++) {
        float v = row[i] * rd + sB2[i];
#pragma unroll
        for (int j = 0; j < 16; j++) t[j] += v * sW1[i * 16 + j];
    }
    float o0 = sb2[0], o1 = sb2[1];
#pragma unroll
    for (int j = 0; j < 16; j++) {
        float tj = t[j] > 0.f ? t[j] : 0.f;
        o0 += tj * sW2[j * 2]; o1 += tj * sW2[j * 2 + 1];
    }
    out[n * 2]     = o0;
    out[n * 2 + 1] = o1;
}

// ---------------- launch --------------------------------------------------------
extern "C" void kernel_launch(void* const* d_in, const int* in_sizes, int n_in,
                              void* d_out, int out_size) {
    const float* x  = (const float*)d_in[0];
    const int*   ei = (const int*)d_in[1];
    int Nn = in_sizes[0] / FIN;
    int E  = in_sizes[1] / 2;

    // locate weight block robustly: gamma(256), beta(256), W1(32768), ...
    int g = -1;
    for (int i = 2; i + 2 < n_in; i++) {
        if (in_sizes[i] == 256 && in_sizes[i + 1] == 256 && in_sizes[i + 2] == FIN * HID2) {
            g = i; break;
        }
    }
    if (g < 0) g = 6;  // fallback to nominal layout
    const float* gamma  = (const float*)d_in[g + 0];
    const float* beta   = (const float*)d_in[g + 1];
    const float* W1     = (const float*)d_in[g + 2];
    const float* a_src1 = (const float*)d_in[g + 3];
    const float* a_dst1 = (const float*)d_in[g + 4];
    const float* b1     = (const float*)d_in[g + 5];
    const float* W2     = (const float*)d_in[g + 6];
    const float* a_src2 = (const float*)d_in[g + 7];
    const float* a_dst2 = (const float*)d_in[g + 8];
    const float* b2     = (const float*)d_in[g + 9];
    const float* Wc1    = (const float*)d_in[g + 10];
    const float* bc1    = (const float*)d_in[g + 11];
    const float* Wc2    = (const float*)d_in[g + 12];
    const float* bc2    = (const float*)d_in[g + 13];
    float* out = (float*)d_out;

    float *p_h1, *p_out1, *p_h2, *p_W1p, *p_c1, *p_zero, *p_denom1;
    cudaGetSymbolAddress((void**)&p_h1,     g_h1);
    cudaGetSymbolAddress((void**)&p_out1,   g_out1);
    cudaGetSymbolAddress((void**)&p_h2,     g_h2);
    cudaGetSymbolAddress((void**)&p_W1p,    g_W1p);
    cudaGetSymbolAddress((void**)&p_c1,     g_c1);
    cudaGetSymbolAddress((void**)&p_zero,   g_zero);
    cudaGetSymbolAddress((void**)&p_denom1, g_denom1);

    int EN = E + Nn;

    // 1) zero accumulators
    init_kernel<<<(Nn * HID2 + 255) / 256, 256>>>(Nn);

    // 2) batchnorm stats + folded weights
    int rowsPerBlock = 256;
    stats_kernel<<<(Nn + rowsPerBlock - 1) / rowsPerBlock, 256>>>(x, Nn, rowsPerBlock);
    prep_scale<<<1, 256>>>(gamma, beta, Nn);
    prep_w1<<<(FIN * HID2 + 255) / 256, 256>>>(W1);
    prep_c1<<<1, HID2>>>(W1);

    // 3) GEMM1: h1 = xn @ W1  (BN folded)
    sgemm_kernel<128, 128, 16, 8, 8, false>
        <<<(Nn + 127) / 128, 256>>>(Nn, HID2, FIN, x, p_W1p, nullptr, nullptr, p_c1, p_h1);

    // 4) conv1: attention coeffs + single fused edge pass (denom + weighted scatter)
    att1_kernel<<<(Nn * 32 + 255) / 256, 256>>>(a_src1, a_dst1, Nn);
    edge_fused1<<<((size_t)EN * 32 + 255) / 256, 256>>>(ei, E, Nn);

    // 5) GEMM2: h2 = elu(out1/denom1 + b1) @ W2   (normalization+activation fused)
    sgemm_kernel<128, 64, 16, 8, 4, true>
        <<<(Nn + 127) / 128, 256>>>(Nn, HH, HID2, p_out1, W2, p_denom1, b1, p_zero, p_h2);

    // 6) conv2: attention coeffs + single fused edge pass
    att2_kernel<<<(Nn * 32 + 255) / 256, 256>>>(a_src2, a_dst2, Nn);
    edge_fused2<<<((size_t)EN * 32 + 255) / 256, 256>>>(ei, E, Nn);

    // 7) final MLP: out = relu((out2/denom2 + b2) @ Wc1 + bc1) @ Wc2 + bc2
    final_kernel<<<(Nn + 255) / 256, 256>>>(b2, Wc1, bc1, Wc2, bc2, out, Nn);
}

// round 5
// speedup vs baseline: 1.5782x; 1.4885x over previous
#include <cuda_runtime.h>
#include <math.h>
#include <stdint.h>

#define FIN 256
#define HID2 128
#define HH  64
#define NMAX 50000
#define EMAX 800000
#define ENMAX (EMAX + NMAX)

__device__ __align__(16) float g_h1  [NMAX * HID2];
__device__ __align__(16) float g_out1[NMAX * HID2];
__device__ __align__(16) float g_h2  [NMAX * HH];
__device__ __align__(16) float g_out2[NMAX * HH];
__device__ __align__(8) float g_asrc1[NMAX * 2], g_adst1[NMAX * 2];
__device__ float g_asrc2[NMAX], g_adst2[NMAX];
__device__ float g_sum[FIN], g_sumsq[FIN];
__device__ float g_scale[FIN], g_shift[FIN];
__device__ __align__(16) float g_W1p[FIN * HID2];
__device__ float g_c1[HID2];
__device__ int g_cnt[NMAX];
__device__ int g_offs[NMAX + 1];
__device__ int g_cursor[NMAX];
__device__ int g_csr[ENMAX];
__device__ int g_bsum[256];
__device__ unsigned g_ctr;

__device__ __forceinline__ float lrelu(float x) { return x > 0.f ? x : 0.2f * x; }
__device__ __forceinline__ float eluf(float x)  { return x > 0.f ? x : expm1f(x); }

__global__ void init_kernel(int Nn) {
    int i = blockIdx.x * blockDim.x + threadIdx.x;
    if (i < Nn) g_cnt[i] = 0;
    if (i < FIN) { g_sum[i] = 0.f; g_sumsq[i] = 0.f; }
    if (i == 0) g_ctr = 0u;
}

__global__ void stats_kernel(const float* __restrict__ x,
                             const float* __restrict__ gamma,
                             const float* __restrict__ beta,
                             int Nn, int rowsPerBlock, int nblocks) {
    int col = threadIdx.x;
    int r0 = blockIdx.x * rowsPerBlock;
    int r1 = min(r0 + rowsPerBlock, Nn);
    float s = 0.f, s2 = 0.f;
    for (int r = r0; r < r1; r++) {
        float v = x[(size_t)r * FIN + col];
        s += v; s2 += v * v;
    }
    atomicAdd(&g_sum[col], s);
    atomicAdd(&g_sumsq[col], s2);
    __threadfence();
    __shared__ int lastBlk;
    if (col == 0) lastBlk = (atomicAdd(&g_ctr, 1u) == (unsigned)(nblocks - 1)) ? 1 : 0;
    __syncthreads();
    if (lastBlk) {
        float inv = 1.f / (float)Nn;
        float mu  = g_sum[col] * inv;
        float var = g_sumsq[col] * inv - mu * mu;
        float rs  = rsqrtf(var + 1e-5f);
        float sc  = rs * gamma[col];
        g_scale[col] = sc;
        g_shift[col] = beta[col] - mu * sc;
    }
}

__global__ void prep_w1c1(const float* __restrict__ W1) {
    if (blockIdx.x < 128) {
        int i = blockIdx.x * 256 + threadIdx.x;
        g_W1p[i] = g_scale[i / HID2] * W1[i];
    } else if (threadIdx.x < HID2) {
        int k = threadIdx.x;
        float s = 0.f;
        for (int f = 0; f < FIN; f++) s += g_shift[f] * W1[f * HID2 + k];
        g_c1[k] = s;
    }
}

// C[M,N] = act(A[M,K]) @ B[K,N] (+ cbias if non-null)
template <int BM, int BN, int BK, int TM, int TN, bool ELU_IN>
__global__ void __launch_bounds__(256)
sgemm_kernel(int M, int N, int K,
             const float* __restrict__ A, const float* __restrict__ B,
             const float* __restrict__ abias, const float* __restrict__ cbias,
             float* __restrict__ C) {
    __shared__ float As[BK][BM + 4];
    __shared__ float Bs[BK][BN];
    const int tid = threadIdx.x;
    const int row0 = blockIdx.x * BM;
    constexpr int TCOLS = BN / TN;
    const int tcol = (tid % TCOLS) * TN;
    const int trow = (tid / TCOLS) * TM;

    float acc[TM][TN];
#pragma unroll
    for (int i = 0; i < TM; i++)
#pragma unroll
        for (int j = 0; j < TN; j++) acc[i][j] = 0.f;

    for (int k0 = 0; k0 < K; k0 += BK) {
#pragma unroll 2
        for (int i = tid; i < BM * BK / 4; i += 256) {
            int r  = i / (BK / 4);
            int c4 = (i % (BK / 4)) * 4;
            int gr = row0 + r;
            float4 v = make_float4(0.f, 0.f, 0.f, 0.f);
            if (gr < M) {
                v = *(const float4*)(A + (size_t)gr * K + k0 + c4);
                if (ELU_IN) {
                    v.x = eluf(v.x + abias[k0 + c4 + 0]);
                    v.y = eluf(v.y + abias[k0 + c4 + 1]);
                    v.z = eluf(v.z + abias[k0 + c4 + 2]);
                    v.w = eluf(v.w + abias[k0 + c4 + 3]);
                }
            }
            As[c4 + 0][r] = v.x; As[c4 + 1][r] = v.y;
            As[c4 + 2][r] = v.z; As[c4 + 3][r] = v.w;
        }
#pragma unroll 2
        for (int i = tid; i < BK * BN / 4; i += 256) {
            int r  = i / (BN / 4);
            int c4 = (i % (BN / 4)) * 4;
            *(float4*)&Bs[r][c4] = *(const float4*)(B + (size_t)(k0 + r) * N + c4);
        }
        __syncthreads();

#pragma unroll
        for (int k = 0; k < BK; k++) {
            float ra[TM], rb[TN];
#pragma unroll
            for (int i = 0; i < TM; i++) ra[i] = As[k][trow + i];
#pragma unroll
            for (int j = 0; j < TN; j++) rb[j] = Bs[k][tcol + j];
#pragma unroll
            for (int i = 0; i < TM; i++)
#pragma unroll
                for (int j = 0; j < TN; j++) acc[i][j] += ra[i] * rb[j];
        }
        __syncthreads();
    }

#pragma unroll
    for (int i = 0; i < TM; i++) {
        int gr = row0 + trow + i;
        if (gr >= M) continue;
#pragma unroll
        for (int j = 0; j < TN; j += 4) {
            float4 v;
            float c0 = cbias ? cbias[tcol + j + 0] : 0.f;
            float c1v = cbias ? cbias[tcol + j + 1] : 0.f;
            float c2 = cbias ? cbias[tcol + j + 2] : 0.f;
            float c3 = cbias ? cbias[tcol + j + 3] : 0.f;
            v.x = acc[i][j + 0] + c0;
            v.y = acc[i][j + 1] + c1v;
            v.z = acc[i][j + 2] + c2;
            v.w = acc[i][j + 3] + c3;
            *(float4*)(C + (size_t)gr * N + tcol + j) = v;
        }
    }
}

__global__ void hist_kernel(const int* __restrict__ ei, int E, int Nn) {
    int i = blockIdx.x * blockDim.x + threadIdx.x;
    if (i >= E + Nn) return;
    int dst = i < E ? ei[E + i] : i - E;
    atomicAdd(&g_cnt[dst], 1);
}

__global__ void scanA(int Nn) {
    __shared__ int sh[256];
    int t = threadIdx.x;
    int i = blockIdx.x * 256 + t;
    int v = (i < Nn) ? g_cnt[i] : 0;
    sh[t] = v; __syncthreads();
#pragma unroll
    for (int o = 1; o < 256; o <<= 1) {
        int add = (t >= o) ? sh[t - o] : 0;
        __syncthreads();
        sh[t] += add;
        __syncthreads();
    }
    if (i < Nn) g_offs[i] = sh[t] - v;
    if (t == 255) g_bsum[blockIdx.x] = sh[255];
}

__global__ void scanB(int nb) {
    __shared__ int sh[256];
    int t = threadIdx.x;
    int v = (t < nb) ? g_bsum[t] : 0;
    sh[t] = v; __syncthreads();
#pragma unroll
    for (int o = 1; o < 256; o <<= 1) {
        int add = (t >= o) ? sh[t - o] : 0;
        __syncthreads();
        sh[t] += add;
        __syncthreads();
    }
    g_bsum[t] = sh[t] - v;
}

__global__ void scanC(int Nn, int EN) {
    int i = blockIdx.x * blockDim.x + threadIdx.x;
    if (i < Nn) {
        int o = g_offs[i] + g_bsum[i >> 8];
        g_offs[i] = o;
        g_cursor[i] = o;
    }
    if (i == 0) g_offs[Nn] = EN;
}

__global__ void fill_kernel(const int* __restrict__ ei, int E, int Nn) {
    int i = blockIdx.x * blockDim.x + threadIdx.x;
    if (i >= E + Nn) return;
    int src = i < E ? ei[i] : i - E;
    int dst = i < E ? ei[E + i] : i - E;
    int pos = atomicAdd(&g_cursor[dst], 1);
    g_csr[pos] = src;
}

__global__ void att1_kernel(const float* __restrict__ a_src,
                            const float* __restrict__ a_dst, int Nn) {
    int gw   = (blockIdx.x * blockDim.x + threadIdx.x) >> 5;
    int lane = threadIdx.x & 31;
    if (gw >= Nn) return;
    const float* row = g_h1 + (size_t)gw * HID2;
    float h0a = row[lane], h0b = row[lane + 32];
    float h1a = row[64 + lane], h1b = row[96 + lane];
    float s0 = h0a * a_src[lane] + h0b * a_src[lane + 32];
    float d0 = h0a * a_dst[lane] + h0b * a_dst[lane + 32];
    float s1 = h1a * a_src[64 + lane] + h1b * a_src[96 + lane];
    float d1 = h1a * a_dst[64 + lane] + h1b * a_dst[96 + lane];
#pragma unroll
    for (int o = 16; o; o >>= 1) {
        s0 += __shfl_down_sync(0xffffffffu, s0, o);
        d0 += __shfl_down_sync(0xffffffffu, d0, o);
        s1 += __shfl_down_sync(0xffffffffu, s1, o);
        d1 += __shfl_down_sync(0xffffffffu, d1, o);
    }
    if (lane == 0) {
        g_asrc1[gw * 2] = s0; g_asrc1[gw * 2 + 1] = s1;
        g_adst1[gw * 2] = d0; g_adst1[gw * 2 + 1] = d1;
    }
}

__global__ void att2_kernel(const float* __restrict__ a_src,
                            const float* __restrict__ a_dst, int Nn) {
    int gw   = (blockIdx.x * blockDim.x + threadIdx.x) >> 5;
    int lane = threadIdx.x & 31;
    if (gw >= Nn) return;
    const float* row = g_h2 + (size_t)gw * HH;
    float ha = row[lane], hb = row[lane + 32];
    float s = ha * a_src[lane] + hb * a_src[lane + 32];
    float d = ha * a_dst[lane] + hb * a_dst[lane + 32];
#pragma unroll
    for (int o = 16; o; o >>= 1) {
        s += __shfl_down_sync(0xffffffffu, s, o);
        d += __shfl_down_sync(0xffffffffu, d, o);
    }
    if (lane == 0) { g_asrc2[gw] = s; g_adst2[gw] = d; }
}

__global__ void gather1(int Nn) {
    int w    = (blockIdx.x * blockDim.x + threadIdx.x) >> 5;
    int lane = threadIdx.x & 31;
    if (w >= Nn) return;
    int s = g_offs[w], e = g_offs[w + 1];
    float2 ad = *(const float2*)&g_adst1[w * 2];
    float4 acc = make_float4(0.f, 0.f, 0.f, 0.f);
    float d0 = 0.f, d1 = 0.f;
    const float* h1base = g_h1 + lane * 4;
    for (int i = s; i < e; i++) {
        int src = __ldg(&g_csr[i]);
        float2 as = *(const float2*)&g_asrc1[src * 2];
        float e0 = __expf(lrelu(as.x + ad.x));
        float e1 = __expf(lrelu(as.y + ad.y));
        d0 += e0; d1 += e1;
        float al = (lane < 16) ? e0 : e1;
        float4 v = *(const float4*)(h1base + (size_t)src * HID2);
        acc.x += al * v.x; acc.y += al * v.y;
        acc.z += al * v.z; acc.w += al * v.w;
    }
    float rd = (lane < 16) ? (1.f / d0) : (1.f / d1);
    acc.x *= rd; acc.y *= rd; acc.z *= rd; acc.w *= rd;
    *(float4*)(g_out1 + (size_t)w * HID2 + lane * 4) = acc;
}

__global__ void gather2(int Nn) {
    int w    = (blockIdx.x * blockDim.x + threadIdx.x) >> 5;
    int lane = threadIdx.x & 31;
    if (w >= Nn) return;
    int s = g_offs[w], e = g_offs[w + 1];
    float ad = g_adst2[w];
    float2 acc = make_float2(0.f, 0.f);
    float d = 0.f;
    const float* h2base = g_h2 + lane * 2;
    for (int i = s; i < e; i++) {
        int src = __ldg(&g_csr[i]);
        float ee = __expf(lrelu(g_asrc2[src] + ad));
        d += ee;
        float2 v = *(const float2*)(h2base + (size_t)src * HH);
        acc.x += ee * v.x; acc.y += ee * v.y;
    }
    float rd = 1.f / d;
    acc.x *= rd; acc.y *= rd;
    *(float2*)(g_out2 + (size_t)w * HH + lane * 2) = acc;
}

__global__ void final_kernel(const float* __restrict__ b2,
                             const float* __restrict__ Wc1,
                             const float* __restrict__ bc1,
                             const float* __restrict__ Wc2,
                             const float* __restrict__ bc2,
                             float* __restrict__ out, int Nn) {
    __shared__ float sW1[64 * 16], sW2[32], sb1[16], sb2[2], sB2[64];
    int tid = threadIdx.x;
    for (int i = tid; i < 64 * 16; i += blockDim.x) sW1[i] = Wc1[i];
    if (tid < 32) sW2[tid] = Wc2[tid];
    if (tid < 16) sb1[tid] = bc1[tid];
    if (tid < 2)  sb2[tid] = bc2[tid];
    if (tid < 64) sB2[tid] = b2[tid];
    __syncthreads();
    int n = blockIdx.x * blockDim.x + tid;
    if (n >= Nn) return;
    const float* row = g_out2 + (size_t)n * HH;
    float t[16];
#pragma unroll
    for (int j = 0; j < 16; j++) t[j] = sb1[j];
#pragma unroll 8
    for (int i = 0; i < 64; i++) {
        float v = row[i] + sB2[i];
#pragma unroll
        for (int j = 0; j < 16; j++) t[j] += v * sW1[i * 16 + j];
    }
    float o0 = sb2[0], o1 = sb2[1];
#pragma unroll
    for (int j = 0; j < 16; j++) {
        float tj = t[j] > 0.f ? t[j] : 0.f;
        o0 += tj * sW2[j * 2]; o1 += tj * sW2[j * 2 + 1];
    }
    out[n * 2]     = o0;
    out[n * 2 + 1] = o1;
}

extern "C" void kernel_launch(void* const* d_in, const int* in_sizes, int n_in,
                              void* d_out, int out_size) {
    const float* x  = (const float*)d_in[0];
    const int*   ei = (const int*)d_in[1];
    int Nn = in_sizes[0] / FIN;
    int E  = in_sizes[1] / 2;

    int g = -1;
    for (int i = 2; i + 2 < n_in; i++) {
        if (in_sizes[i] == 256 && in_sizes[i + 1] == 256 && in_sizes[i + 2] == FIN * HID2) {
            g = i; break;
        }
    }
    if (g < 0) g = 6;
    const float* gamma  = (const float*)d_in[g + 0];
    const float* beta   = (const float*)d_in[g + 1];
    const float* W1     = (const float*)d_in[g + 2];
    const float* a_src1 = (const float*)d_in[g + 3];
    const float* a_dst1 = (const float*)d_in[g + 4];
    const float* b1     = (const float*)d_in[g + 5];
    const float* W2     = (const float*)d_in[g + 6];
    const float* a_src2 = (const float*)d_in[g + 7];
    const float* a_dst2 = (const float*)d_in[g + 8];
    const float* b2     = (const float*)d_in[g + 9];
    const float* Wc1    = (const float*)d_in[g + 10];
    const float* bc1    = (const float*)d_in[g + 11];
    const float* Wc2    = (const float*)d_in[g + 12];
    const float* bc2    = (const float*)d_in[g + 13];
    float* out = (float*)d_out;

    float *p_h1, *p_out1, *p_h2, *p_W1p, *p_c1;
    cudaGetSymbolAddress((void**)&p_h1,   g_h1);
    cudaGetSymbolAddress((void**)&p_out1, g_out1);
    cudaGetSymbolAddress((void**)&p_h2,   g_h2);
    cudaGetSymbolAddress((void**)&p_W1p,  g_W1p);
    cudaGetSymbolAddress((void**)&p_c1,   g_c1);

    int EN = E + Nn;
    int nScanBlocks = (Nn + 255) / 256;

    init_kernel<<<(Nn + 255) / 256, 256>>>(Nn);

    int rowsPerBlock = 256;
    int nStatBlocks = (Nn + rowsPerBlock - 1) / rowsPerBlock;
    stats_kernel<<<nStatBlocks, 256>>>(x, gamma, beta, Nn, rowsPerBlock, nStatBlocks);

    prep_w1c1<<<129, 256>>>(W1);

    sgemm_kernel<128, 128, 16, 8, 8, false>
        <<<(Nn + 127) / 128, 256>>>(Nn, HID2, FIN, x, p_W1p, nullptr, p_c1, p_h1);

    hist_kernel<<<(EN + 255) / 256, 256>>>(ei, E, Nn);
    scanA<<<nScanBlocks, 256>>>(Nn);
    scanB<<<1, 256>>>(nScanBlocks);
    scanC<<<(Nn + 255) / 256, 256>>>(Nn, EN);
    fill_kernel<<<(EN + 255) / 256, 256>>>(ei, E, Nn);

    att1_kernel<<<(Nn * 32 + 255) / 256, 256>>>(a_src1, a_dst1, Nn);
    gather1<<<((size_t)Nn * 32 + 255) / 256, 256>>>(Nn);

    sgemm_kernel<128, 64, 16, 8, 4, true>
        <<<(Nn + 127) / 128, 256>>>(Nn, HH, HID2, p_out1, W2, b1, nullptr, p_h2);

    att2_kernel<<<(Nn * 32 + 255) / 256, 256>>>(a_src2, a_dst2, Nn);
    gather2<<<((size_t)Nn * 32 + 255) / 256, 256>>>(Nn);

    final_kernel<<<(Nn + 255) / 256, 256>>>(b2, Wc1, bc1, Wc2, bc2, out, Nn);
}

// round 6
// speedup vs baseline: 1.6423x; 1.0406x over previous
#include <cuda_runtime.h>
#include <math.h>
#include <stdint.h>

#define FIN 256
#define HID2 128
#define HH  64
#define NMAX 50000
#define EMAX 800000
#define ENMAX (EMAX + NMAX)

__device__ __align__(16) float g_h1  [NMAX * HID2];
__device__ __align__(16) float g_out1[NMAX * HID2];   // elu(conv1_out + b1), pre-activated
__device__ __align__(16) float g_h2  [NMAX * HH];
__device__ __align__(16) float g_out2[NMAX * HH];
__device__ __align__(8) float g_asrc1[NMAX * 2], g_adst1[NMAX * 2];
__device__ float g_asrc2[NMAX], g_adst2[NMAX];
__device__ float g_sum[FIN], g_sumsq[FIN];
__device__ float g_scale[FIN], g_shift[FIN];
__device__ __align__(16) float g_W1p[FIN * HID2];
__device__ float g_c1[HID2];
__device__ int g_cnt[NMAX];
__device__ int g_offs[NMAX + 1];
__device__ int g_cursor[NMAX];
__device__ int g_csr[ENMAX];
__device__ int g_bsum[256];
__device__ unsigned g_ctr;

__device__ __forceinline__ float lrelu(float x) { return x > 0.f ? x : 0.2f * x; }
__device__ __forceinline__ float eluf(float x)  { return x > 0.f ? x : expm1f(x); }

// ---- cp.async helpers ---------------------------------------------------------
__device__ __forceinline__ void cpasync16(uint32_t dst_smem, const void* src, int src_bytes) {
    asm volatile("cp.async.cg.shared.global [%0], [%1], 16, %2;"
                 :: "r"(dst_smem), "l"(src), "r"(src_bytes));
}
__device__ __forceinline__ void cp_commit() {
    asm volatile("cp.async.commit_group;" ::: "memory");
}
__device__ __forceinline__ void cp_wait0() {
    asm volatile("cp.async.wait_group 0;" ::: "memory");
}

__global__ void init_kernel(int Nn) {
    int i = blockIdx.x * blockDim.x + threadIdx.x;
    if (i < Nn) g_cnt[i] = 0;
    if (i < FIN) { g_sum[i] = 0.f; g_sumsq[i] = 0.f; }
    if (i == 0) g_ctr = 0u;
}

__global__ void stats_kernel(const float* __restrict__ x,
                             const float* __restrict__ gamma,
                             const float* __restrict__ beta,
                             int Nn, int rowsPerBlock, int nblocks) {
    int col = threadIdx.x;
    int r0 = blockIdx.x * rowsPerBlock;
    int r1 = min(r0 + rowsPerBlock, Nn);
    float s = 0.f, s2 = 0.f;
    for (int r = r0; r < r1; r++) {
        float v = x[(size_t)r * FIN + col];
        s += v; s2 += v * v;
    }
    atomicAdd(&g_sum[col], s);
    atomicAdd(&g_sumsq[col], s2);
    __threadfence();
    __shared__ int lastBlk;
    if (col == 0) lastBlk = (atomicAdd(&g_ctr, 1u) == (unsigned)(nblocks - 1)) ? 1 : 0;
    __syncthreads();
    if (lastBlk) {
        float inv = 1.f / (float)Nn;
        float mu  = g_sum[col] * inv;
        float var = g_sumsq[col] * inv - mu * mu;
        float rs  = rsqrtf(var + 1e-5f);
        float sc  = rs * gamma[col];
        g_scale[col] = sc;
        g_shift[col] = beta[col] - mu * sc;
    }
}

__global__ void prep_w1c1(const float* __restrict__ W1) {
    if (blockIdx.x < 128) {
        int i = blockIdx.x * 256 + threadIdx.x;
        g_W1p[i] = g_scale[i / HID2] * W1[i];
    } else if (threadIdx.x < HID2) {
        int k = threadIdx.x;
        float s = 0.f;
        for (int f = 0; f < FIN; f++) s += g_shift[f] * W1[f * HID2 + k];
        g_c1[k] = s;
    }
}

// ---------- cp.async double-buffered SGEMM: C = A[M,K] @ B[K,N] (+ cbias) ------
template <int BM, int BN, int BK, int TM, int TN>
__global__ void __launch_bounds__(256, 2)
sgemm_ca(int M, int N, int K,
         const float* __restrict__ A, const float* __restrict__ B,
         const float* __restrict__ cbias, float* __restrict__ C) {
    __shared__ float As[2][BM][BK];   // row-major: K contiguous (cp.async friendly)
    __shared__ float Bs[2][BK][BN];
    const int tid  = threadIdx.x;
    const int row0 = blockIdx.x * BM;
    constexpr int TCOLS = BN / TN;
    const int tcol = (tid % TCOLS) * TN;
    const int trow = (tid / TCOLS) * TM;
    constexpr int NA4 = BM * BK / 4;   // float4s in A tile
    constexpr int NB4 = BK * BN / 4;
    constexpr int KC4 = BK / 4;

    uint32_t sA0 = (uint32_t)__cvta_generic_to_shared(&As[0][0][0]);
    uint32_t sA1 = (uint32_t)__cvta_generic_to_shared(&As[1][0][0]);
    uint32_t sB0 = (uint32_t)__cvta_generic_to_shared(&Bs[0][0][0]);
    uint32_t sB1 = (uint32_t)__cvta_generic_to_shared(&Bs[1][0][0]);

    float acc[TM][TN];
#pragma unroll
    for (int i = 0; i < TM; i++)
#pragma unroll
        for (int j = 0; j < TN; j++) acc[i][j] = 0.f;

    const int ntiles = K / BK;

    // tile copy: issue cp.asyncs for tile t into buffer buf
    auto issue = [&](int t, int buf) {
        int k0 = t * BK;
        uint32_t sA = buf ? sA1 : sA0;
        uint32_t sB = buf ? sB1 : sB0;
#pragma unroll
        for (int i = tid; i < NA4; i += 256) {
            int r  = i / KC4;
            int c4 = (i % KC4) * 4;
            int gr = row0 + r;
            const float* src = A + (size_t)(gr < M ? gr : 0) * K + k0 + c4;
            cpasync16(sA + (uint32_t)(r * BK + c4) * 4u, src, gr < M ? 16 : 0);
        }
#pragma unroll
        for (int i = tid; i < NB4; i += 256) {
            int r  = i / (BN / 4);
            int c4 = (i % (BN / 4)) * 4;
            cpasync16(sB + (uint32_t)(r * BN + c4) * 4u,
                      B + (size_t)(k0 + r) * N + c4, 16);
        }
        cp_commit();
    };

    issue(0, 0);

    for (int t = 0; t < ntiles; t++) {
        int buf = t & 1;
        cp_wait0();
        __syncthreads();          // tile t visible; all threads past compute(t-1)
        if (t + 1 < ntiles) issue(t + 1, buf ^ 1);

#pragma unroll
        for (int k = 0; k < BK; k++) {
            float ra[TM], rb[TN];
#pragma unroll
            for (int i = 0; i < TM; i++) ra[i] = As[buf][trow + i][k];
#pragma unroll
            for (int j = 0; j < TN; j += 4) {
                float4 b4 = *(const float4*)&Bs[buf][k][tcol + j];
                rb[j] = b4.x; rb[j + 1] = b4.y; rb[j + 2] = b4.z; rb[j + 3] = b4.w;
            }
#pragma unroll
            for (int i = 0; i < TM; i++)
#pragma unroll
                for (int j = 0; j < TN; j++) acc[i][j] += ra[i] * rb[j];
        }
        __syncthreads();          // all threads done reading buf before overwrite
    }

#pragma unroll
    for (int i = 0; i < TM; i++) {
        int gr = row0 + trow + i;
        if (gr >= M) continue;
#pragma unroll
        for (int j = 0; j < TN; j += 4) {
            float4 v;
            float c0 = cbias ? cbias[tcol + j + 0] : 0.f;
            float c1v = cbias ? cbias[tcol + j + 1] : 0.f;
            float c2 = cbias ? cbias[tcol + j + 2] : 0.f;
            float c3 = cbias ? cbias[tcol + j + 3] : 0.f;
            v.x = acc[i][j + 0] + c0;
            v.y = acc[i][j + 1] + c1v;
            v.z = acc[i][j + 2] + c2;
            v.w = acc[i][j + 3] + c3;
            *(float4*)(C + (size_t)gr * N + tcol + j) = v;
        }
    }
}

__global__ void hist_kernel(const int* __restrict__ ei, int E, int Nn) {
    int i = blockIdx.x * blockDim.x + threadIdx.x;
    if (i >= E + Nn) return;
    int dst = i < E ? ei[E + i] : i - E;
    atomicAdd(&g_cnt[dst], 1);
}

__global__ void scanA(int Nn) {
    __shared__ int sh[256];
    int t = threadIdx.x;
    int i = blockIdx.x * 256 + t;
    int v = (i < Nn) ? g_cnt[i] : 0;
    sh[t] = v; __syncthreads();
#pragma unroll
    for (int o = 1; o < 256; o <<= 1) {
        int add = (t >= o) ? sh[t - o] : 0;
        __syncthreads();
        sh[t] += add;
        __syncthreads();
    }
    if (i < Nn) g_offs[i] = sh[t] - v;
    if (t == 255) g_bsum[blockIdx.x] = sh[255];
}

__global__ void scanB(int nb) {
    __shared__ int sh[256];
    int t = threadIdx.x;
    int v = (t < nb) ? g_bsum[t] : 0;
    sh[t] = v; __syncthreads();
#pragma unroll
    for (int o = 1; o < 256; o <<= 1) {
        int add = (t >= o) ? sh[t - o] : 0;
        __syncthreads();
        sh[t] += add;
        __syncthreads();
    }
    g_bsum[t] = sh[t] - v;
}

__global__ void scanC(int Nn, int EN) {
    int i = blockIdx.x * blockDim.x + threadIdx.x;
    if (i < Nn) {
        int o = g_offs[i] + g_bsum[i >> 8];
        g_offs[i] = o;
        g_cursor[i] = o;
    }
    if (i == 0) g_offs[Nn] = EN;
}

__global__ void fill_kernel(const int* __restrict__ ei, int E, int Nn) {
    int i = blockIdx.x * blockDim.x + threadIdx.x;
    if (i >= E + Nn) return;
    int src = i < E ? ei[i] : i - E;
    int dst = i < E ? ei[E + i] : i - E;
    int pos = atomicAdd(&g_cursor[dst], 1);
    g_csr[pos] = src;
}

__global__ void att1_kernel(const float* __restrict__ a_src,
                            const float* __restrict__ a_dst, int Nn) {
    int gw   = (blockIdx.x * blockDim.x + threadIdx.x) >> 5;
    int lane = threadIdx.x & 31;
    if (gw >= Nn) return;
    const float* row = g_h1 + (size_t)gw * HID2;
    float h0a = row[lane], h0b = row[lane + 32];
    float h1a = row[64 + lane], h1b = row[96 + lane];
    float s0 = h0a * a_src[lane] + h0b * a_src[lane + 32];
    float d0 = h0a * a_dst[lane] + h0b * a_dst[lane + 32];
    float s1 = h1a * a_src[64 + lane] + h1b * a_src[96 + lane];
    float d1 = h1a * a_dst[64 + lane] + h1b * a_dst[96 + lane];
#pragma unroll
    for (int o = 16; o; o >>= 1) {
        s0 += __shfl_down_sync(0xffffffffu, s0, o);
        d0 += __shfl_down_sync(0xffffffffu, d0, o);
        s1 += __shfl_down_sync(0xffffffffu, s1, o);
        d1 += __shfl_down_sync(0xffffffffu, d1, o);
    }
    if (lane == 0) {
        g_asrc1[gw * 2] = s0; g_asrc1[gw * 2 + 1] = s1;
        g_adst1[gw * 2] = d0; g_adst1[gw * 2 + 1] = d1;
    }
}

__global__ void att2_kernel(const float* __restrict__ a_src,
                            const float* __restrict__ a_dst, int Nn) {
    int gw   = (blockIdx.x * blockDim.x + threadIdx.x) >> 5;
    int lane = threadIdx.x & 31;
    if (gw >= Nn) return;
    const float* row = g_h2 + (size_t)gw * HH;
    float ha = row[lane], hb = row[lane + 32];
    float s = ha * a_src[lane] + hb * a_src[lane + 32];
    float d = ha * a_dst[lane] + hb * a_dst[lane + 32];
#pragma unroll
    for (int o = 16; o; o >>= 1) {
        s += __shfl_down_sync(0xffffffffu, s, o);
        d += __shfl_down_sync(0xffffffffu, d, o);
    }
    if (lane == 0) { g_asrc2[gw] = s; g_adst2[gw] = d; }
}

// gather1: softmax-weighted aggregation + fused elu(.+b1) epilogue
__global__ void gather1(const float* __restrict__ b1, int Nn) {
    int w    = (blockIdx.x * blockDim.x + threadIdx.x) >> 5;
    int lane = threadIdx.x & 31;
    if (w >= Nn) return;
    int s = g_offs[w], e = g_offs[w + 1];
    float2 ad = *(const float2*)&g_adst1[w * 2];
    float4 acc = make_float4(0.f, 0.f, 0.f, 0.f);
    float d0 = 0.f, d1 = 0.f;
    const float* h1base = g_h1 + lane * 4;
    for (int i = s; i < e; i++) {
        int src = __ldg(&g_csr[i]);
        float2 as = *(const float2*)&g_asrc1[src * 2];
        float e0 = __expf(lrelu(as.x + ad.x));
        float e1 = __expf(lrelu(as.y + ad.y));
        d0 += e0; d1 += e1;
        float al = (lane < 16) ? e0 : e1;
        float4 v = *(const float4*)(h1base + (size_t)src * HID2);
        acc.x += al * v.x; acc.y += al * v.y;
        acc.z += al * v.z; acc.w += al * v.w;
    }
    float rd = (lane < 16) ? (1.f / d0) : (1.f / d1);
    float4 bb = *(const float4*)(b1 + lane * 4);
    acc.x = eluf(acc.x * rd + bb.x);
    acc.y = eluf(acc.y * rd + bb.y);
    acc.z = eluf(acc.z * rd + bb.z);
    acc.w = eluf(acc.w * rd + bb.w);
    *(float4*)(g_out1 + (size_t)w * HID2 + lane * 4) = acc;
}

__global__ void gather2(int Nn) {
    int w    = (blockIdx.x * blockDim.x + threadIdx.x) >> 5;
    int lane = threadIdx.x & 31;
    if (w >= Nn) return;
    int s = g_offs[w], e = g_offs[w + 1];
    float ad = g_adst2[w];
    float2 acc = make_float2(0.f, 0.f);
    float d = 0.f;
    const float* h2base = g_h2 + lane * 2;
    for (int i = s; i < e; i++) {
        int src = __ldg(&g_csr[i]);
        float ee = __expf(lrelu(g_asrc2[src] + ad));
        d += ee;
        float2 v = *(const float2*)(h2base + (size_t)src * HH);
        acc.x += ee * v.x; acc.y += ee * v.y;
    }
    float rd = 1.f / d;
    acc.x *= rd; acc.y *= rd;
    *(float2*)(g_out2 + (size_t)w * HH + lane * 2) = acc;
}

__global__ void final_kernel(const float* __restrict__ b2,
                             const float* __restrict__ Wc1,
                             const float* __restrict__ bc1,
                             const float* __restrict__ Wc2,
                             const float* __restrict__ bc2,
                             float* __restrict__ out, int Nn) {
    __shared__ float sW1[64 * 16], sW2[32], sb1[16], sb2[2], sB2[64];
    int tid = threadIdx.x;
    for (int i = tid; i < 64 * 16; i += blockDim.x) sW1[i] = Wc1[i];
    if (tid < 32) sW2[tid] = Wc2[tid];
    if (tid < 16) sb1[tid] = bc1[tid];
    if (tid < 2)  sb2[tid] = bc2[tid];
    if (tid < 64) sB2[tid] = b2[tid];
    __syncthreads();
    int n = blockIdx.x * blockDim.x + tid;
    if (n >= Nn) return;
    const float* row = g_out2 + (size_t)n * HH;
    float t[16];
#pragma unroll
    for (int j = 0; j < 16; j++) t[j] = sb1[j];
#pragma unroll 8
    for (int i = 0; i < 64; i++) {
        float v = row[i] + sB2[i];
#pragma unroll
        for (int j = 0; j < 16; j++) t[j] += v * sW1[i * 16 + j];
    }
    float o0 = sb2[0], o1 = sb2[1];
#pragma unroll
    for (int j = 0; j < 16; j++) {
        float tj = t[j] > 0.f ? t[j] : 0.f;
        o0 += tj * sW2[j * 2]; o1 += tj * sW2[j * 2 + 1];
    }
    out[n * 2]     = o0;
    out[n * 2 + 1] = o1;
}

extern "C" void kernel_launch(void* const* d_in, const int* in_sizes, int n_in,
                              void* d_out, int out_size) {
    const float* x  = (const float*)d_in[0];
    const int*   ei = (const int*)d_in[1];
    int Nn = in_sizes[0] / FIN;
    int E  = in_sizes[1] / 2;

    int g = -1;
    for (int i = 2; i + 2 < n_in; i++) {
        if (in_sizes[i] == 256 && in_sizes[i + 1] == 256 && in_sizes[i + 2] == FIN * HID2) {
            g = i; break;
        }
    }
    if (g < 0) g = 6;
    const float* gamma  = (const float*)d_in[g + 0];
    const float* beta   = (const float*)d_in[g + 1];
    const float* W1     = (const float*)d_in[g + 2];
    const float* a_src1 = (const float*)d_in[g + 3];
    const float* a_dst1 = (const float*)d_in[g + 4];
    const float* b1     = (const float*)d_in[g + 5];
    const float* W2     = (const float*)d_in[g + 6];
    const float* a_src2 = (const float*)d_in[g + 7];
    const float* a_dst2 = (const float*)d_in[g + 8];
    const float* b2     = (const float*)d_in[g + 9];
    const float* Wc1    = (const float*)d_in[g + 10];
    const float* bc1    = (const float*)d_in[g + 11];
    const float* Wc2    = (const float*)d_in[g + 12];
    const float* bc2    = (const float*)d_in[g + 13];
    float* out = (float*)d_out;

    float *p_h1, *p_out1, *p_h2, *p_W1p, *p_c1;
    cudaGetSymbolAddress((void**)&p_h1,   g_h1);
    cudaGetSymbolAddress((void**)&p_out1, g_out1);
    cudaGetSymbolAddress((void**)&p_h2,   g_h2);
    cudaGetSymbolAddress((void**)&p_W1p,  g_W1p);
    cudaGetSymbolAddress((void**)&p_c1,   g_c1);

    int EN = E + Nn;
    int nScanBlocks = (Nn + 255) / 256;

    init_kernel<<<(Nn + 255) / 256, 256>>>(Nn);

    int rowsPerBlock = 256;
    int nStatBlocks = (Nn + rowsPerBlock - 1) / rowsPerBlock;
    stats_kernel<<<nStatBlocks, 256>>>(x, gamma, beta, Nn, rowsPerBlock, nStatBlocks);

    prep_w1c1<<<129, 256>>>(W1);

    // GEMM1: h1 = xn @ W1 (BN folded), cp.async double-buffered
    sgemm_ca<128, 128, 16, 8, 8>
        <<<(Nn + 127) / 128, 256>>>(Nn, HID2, FIN, x, p_W1p, p_c1, p_h1);

    hist_kernel<<<(EN + 255) / 256, 256>>>(ei, E, Nn);
    scanA<<<nScanBlocks, 256>>>(Nn);
    scanB<<<1, 256>>>(nScanBlocks);
    scanC<<<(Nn + 255) / 256, 256>>>(Nn, EN);
    fill_kernel<<<(EN + 255) / 256, 256>>>(ei, E, Nn);

    att1_kernel<<<(Nn * 32 + 255) / 256, 256>>>(a_src1, a_dst1, Nn);
    gather1<<<((size_t)Nn * 32 + 255) / 256, 256>>>(b1, Nn);

    // GEMM2: h2 = out1 @ W2 (A already elu(.+b1)-activated by gather1)
    sgemm_ca<128, 64, 16, 8, 4>
        <<<(Nn + 127) / 128, 256>>>(Nn, HH, HID2, p_out1, W2, nullptr, p_h2);

    att2_kernel<<<(Nn * 32 + 255) / 256, 256>>>(a_src2, a_dst2, Nn);
    gather2<<<((size_t)Nn * 32 + 255) / 256, 256>>>(Nn);

    final_kernel<<<(Nn + 255) / 256, 256>>>(b2, Wc1, bc1, Wc2, bc2, out, Nn);
}

// round 7
// speedup vs baseline: 1.7929x; 1.0917x over previous
#include <cuda_runtime.h>
#include <math.h>
#include <stdint.h>

#define FIN 256
#define HID2 128
#define HH  64
#define NMAX 50000
#define EMAX 800000
#define ENMAX (EMAX + NMAX)

__device__ __align__(16) float g_h1  [NMAX * HID2];
__device__ __align__(16) float g_out1[NMAX * HID2];   // elu(conv1_out + b1), pre-activated
__device__ __align__(16) float g_h2  [NMAX * HH];
__device__ __align__(16) float g_out2[NMAX * HH];
__device__ __align__(8) float g_asrc1[NMAX * 2], g_adst1[NMAX * 2];
__device__ float g_asrc2[NMAX], g_adst2[NMAX];
__device__ float g_sum[FIN], g_sumsq[FIN];
__device__ float g_scale[FIN], g_shift[FIN];
__device__ __align__(16) float g_W1p[FIN * HID2];
__device__ float g_c1[HID2];
__device__ int g_cnt[NMAX];
__device__ int g_offs[NMAX + 1];
__device__ int g_cursor[NMAX];
__device__ int g_csr[ENMAX];
__device__ int g_bsum[256];
__device__ unsigned g_ctr;

__device__ __forceinline__ float lrelu(float x) { return x > 0.f ? x : 0.2f * x; }
__device__ __forceinline__ float eluf(float x)  { return x > 0.f ? x : expm1f(x); }

// ---- cp.async helpers ---------------------------------------------------------
__device__ __forceinline__ void cpasync16(uint32_t dst_smem, const void* src, int src_bytes) {
    asm volatile("cp.async.cg.shared.global [%0], [%1], 16, %2;"
                 :: "r"(dst_smem), "l"(src), "r"(src_bytes));
}
__device__ __forceinline__ void cp_commit() {
    asm volatile("cp.async.commit_group;" ::: "memory");
}
__device__ __forceinline__ void cp_wait0() {
    asm volatile("cp.async.wait_group 0;" ::: "memory");
}

// ---- tf32 helpers -------------------------------------------------------------
__device__ __forceinline__ uint32_t f2tf32(float x) {
    uint32_t r;
    asm("cvt.rna.tf32.f32 %0, %1;" : "=r"(r) : "f"(x));
    return r;
}
__device__ __forceinline__ void split_tf32(float v, uint32_t& hi, uint32_t& lo) {
    hi = f2tf32(v);
    lo = f2tf32(v - __uint_as_float(hi));
}
__device__ __forceinline__ void mma_tf32(float* d, const uint32_t* a, const uint32_t* b) {
    asm volatile(
        "mma.sync.aligned.m16n8k8.row.col.f32.tf32.tf32.f32 "
        "{%0,%1,%2,%3}, {%4,%5,%6,%7}, {%8,%9}, {%0,%1,%2,%3};"
        : "+f"(d[0]), "+f"(d[1]), "+f"(d[2]), "+f"(d[3])
        : "r"(a[0]), "r"(a[1]), "r"(a[2]), "r"(a[3]), "r"(b[0]), "r"(b[1]));
}

__global__ void init_kernel(int Nn) {
    int i = blockIdx.x * blockDim.x + threadIdx.x;
    if (i < Nn) g_cnt[i] = 0;
    if (i < FIN) { g_sum[i] = 0.f; g_sumsq[i] = 0.f; }
    if (i == 0) g_ctr = 0u;
}

__global__ void stats_kernel(const float* __restrict__ x,
                             const float* __restrict__ gamma,
                             const float* __restrict__ beta,
                             int Nn, int rowsPerBlock, int nblocks) {
    int col = threadIdx.x;
    int r0 = blockIdx.x * rowsPerBlock;
    int r1 = min(r0 + rowsPerBlock, Nn);
    float s = 0.f, s2 = 0.f;
    for (int r = r0; r < r1; r++) {
        float v = x[(size_t)r * FIN + col];
        s += v; s2 += v * v;
    }
    atomicAdd(&g_sum[col], s);
    atomicAdd(&g_sumsq[col], s2);
    __threadfence();
    __shared__ int lastBlk;
    if (col == 0) lastBlk = (atomicAdd(&g_ctr, 1u) == (unsigned)(nblocks - 1)) ? 1 : 0;
    __syncthreads();
    if (lastBlk) {
        float inv = 1.f / (float)Nn;
        float mu  = g_sum[col] * inv;
        float var = g_sumsq[col] * inv - mu * mu;
        float rs  = rsqrtf(var + 1e-5f);
        float sc  = rs * gamma[col];
        g_scale[col] = sc;
        g_shift[col] = beta[col] - mu * sc;
    }
}

__global__ void prep_w1c1(const float* __restrict__ W1) {
    if (blockIdx.x < 128) {
        int i = blockIdx.x * 256 + threadIdx.x;
        g_W1p[i] = g_scale[i / HID2] * W1[i];
    } else if (threadIdx.x < HID2) {
        int k = threadIdx.x;
        float s = 0.f;
        for (int f = 0; f < FIN; f++) s += g_shift[f] * W1[f * HID2 + k];
        g_c1[k] = s;
    }
}

// --------- 3xTF32 tensor-core GEMM: C[M,N] = A[M,K] @ B[K,N] (+ cbias) ---------
// 256 threads = 8 warps as 2(m) x 4(n). Warp tile 64 x (BN/4). mma m16n8k8.
template <int BM, int BN, int BK>
__global__ void __launch_bounds__(256, 2)
gemm_tc(int M, int N, int K,
        const float* __restrict__ A, const float* __restrict__ B,
        const float* __restrict__ cbias, float* __restrict__ C) {
    constexpr int WM = BM / 2;          // 64
    constexpr int WN = BN / 4;          // 32 (BN=128) or 16 (BN=64)
    constexpr int AM = WM / 16;         // 4 m-frags
    constexpr int AN = WN / 8;          // 4 or 2 n-frags
    constexpr int APAD = 4;             // (BK+4) stride, conflict-free, 16B-aligned
    constexpr int BPAD = 8;             // (BN+8) stride, conflict-free, 16B-aligned
    __shared__ float As[2][BM][BK + APAD];
    __shared__ float Bs[2][BK][BN + BPAD];

    const int tid  = threadIdx.x;
    const int wid  = tid >> 5;
    const int lane = tid & 31;
    const int wm   = wid >> 2;          // 0..1
    const int wn   = wid & 3;           // 0..3
    const int row0 = blockIdx.x * BM;
    const int lr   = lane >> 2;         // 0..7
    const int lc   = lane & 3;          // 0..3

    uint32_t sA[2], sB[2];
    sA[0] = (uint32_t)__cvta_generic_to_shared(&As[0][0][0]);
    sA[1] = (uint32_t)__cvta_generic_to_shared(&As[1][0][0]);
    sB[0] = (uint32_t)__cvta_generic_to_shared(&Bs[0][0][0]);
    sB[1] = (uint32_t)__cvta_generic_to_shared(&Bs[1][0][0]);

    float acc[AM][AN][4];
#pragma unroll
    for (int i = 0; i < AM; i++)
#pragma unroll
        for (int j = 0; j < AN; j++)
#pragma unroll
            for (int q = 0; q < 4; q++) acc[i][j][q] = 0.f;

    const int ntiles = K / BK;
    constexpr int NA4 = BM * BK / 4;
    constexpr int NB4 = BK * BN / 4;
    constexpr int KC4 = BK / 4;

    auto issue = [&](int t, int buf) {
        int k0 = t * BK;
#pragma unroll
        for (int i = tid; i < NA4; i += 256) {
            int r  = i / KC4;
            int c4 = (i % KC4) * 4;
            int gr = row0 + r;
            const float* src = A + (size_t)(gr < M ? gr : 0) * K + k0 + c4;
            cpasync16(sA[buf] + (uint32_t)(r * (BK + APAD) + c4) * 4u, src, gr < M ? 16 : 0);
        }
#pragma unroll
        for (int i = tid; i < NB4; i += 256) {
            int r  = i / (BN / 4);
            int c4 = (i % (BN / 4)) * 4;
            cpasync16(sB[buf] + (uint32_t)(r * (BN + BPAD) + c4) * 4u,
                      B + (size_t)(k0 + r) * N + c4, 16);
        }
        cp_commit();
    };

    issue(0, 0);

    for (int t = 0; t < ntiles; t++) {
        int buf = t & 1;
        cp_wait0();
        __syncthreads();
        if (t + 1 < ntiles) issue(t + 1, buf ^ 1);

#pragma unroll
        for (int kk = 0; kk < BK; kk += 8) {
            uint32_t Ahi[AM][4], Alo[AM][4];
#pragma unroll
            for (int mi = 0; mi < AM; mi++) {
                int rb = wm * WM + mi * 16 + lr;
                int cb = kk + lc;
                split_tf32(As[buf][rb    ][cb    ], Ahi[mi][0], Alo[mi][0]);
                split_tf32(As[buf][rb + 8][cb    ], Ahi[mi][1], Alo[mi][1]);
                split_tf32(As[buf][rb    ][cb + 4], Ahi[mi][2], Alo[mi][2]);
                split_tf32(As[buf][rb + 8][cb + 4], Ahi[mi][3], Alo[mi][3]);
            }
            uint32_t Bhi[AN][2], Blo[AN][2];
#pragma unroll
            for (int ni = 0; ni < AN; ni++) {
                int nb = wn * WN + ni * 8 + lr;
                int kb = kk + lc;
                split_tf32(Bs[buf][kb    ][nb], Bhi[ni][0], Blo[ni][0]);
                split_tf32(Bs[buf][kb + 4][nb], Bhi[ni][1], Blo[ni][1]);
            }
#pragma unroll
            for (int mi = 0; mi < AM; mi++)
#pragma unroll
                for (int ni = 0; ni < AN; ni++) {
                    mma_tf32(acc[mi][ni], Ahi[mi], Bhi[ni]);
                    mma_tf32(acc[mi][ni], Ahi[mi], Blo[ni]);
                    mma_tf32(acc[mi][ni], Alo[mi], Bhi[ni]);
                }
        }
        __syncthreads();
    }

    // epilogue: c0,c1 at (r, c..c+1), c2,c3 at (r+8, c..c+1)
#pragma unroll
    for (int mi = 0; mi < AM; mi++) {
#pragma unroll
        for (int ni = 0; ni < AN; ni++) {
            int r = row0 + wm * WM + mi * 16 + lr;
            int c = wn * WN + ni * 8 + 2 * lc;
            float b0 = cbias ? cbias[c] : 0.f;
            float b1 = cbias ? cbias[c + 1] : 0.f;
            if (r < M) {
                float2 v0 = make_float2(acc[mi][ni][0] + b0, acc[mi][ni][1] + b1);
                *(float2*)(C + (size_t)r * N + c) = v0;
            }
            if (r + 8 < M) {
                float2 v1 = make_float2(acc[mi][ni][2] + b0, acc[mi][ni][3] + b1);
                *(float2*)(C + (size_t)(r + 8) * N + c) = v1;
            }
        }
    }
}

__global__ void hist_kernel(const int* __restrict__ ei, int E, int Nn) {
    int i = blockIdx.x * blockDim.x + threadIdx.x;
    if (i >= E + Nn) return;
    int dst = i < E ? ei[E + i] : i - E;
    atomicAdd(&g_cnt[dst], 1);
}

__global__ void scanA(int Nn) {
    __shared__ int sh[256];
    int t = threadIdx.x;
    int i = blockIdx.x * 256 + t;
    int v = (i < Nn) ? g_cnt[i] : 0;
    sh[t] = v; __syncthreads();
#pragma unroll
    for (int o = 1; o < 256; o <<= 1) {
        int add = (t >= o) ? sh[t - o] : 0;
        __syncthreads();
        sh[t] += add;
        __syncthreads();
    }
    if (i < Nn) g_offs[i] = sh[t] - v;
    if (t == 255) g_bsum[blockIdx.x] = sh[255];
}

__global__ void scanB(int nb) {
    __shared__ int sh[256];
    int t = threadIdx.x;
    int v = (t < nb) ? g_bsum[t] : 0;
    sh[t] = v; __syncthreads();
#pragma unroll
    for (int o = 1; o < 256; o <<= 1) {
        int add = (t >= o) ? sh[t - o] : 0;
        __syncthreads();
        sh[t] += add;
        __syncthreads();
    }
    g_bsum[t] = sh[t] - v;
}

__global__ void scanC(int Nn, int EN) {
    int i = blockIdx.x * blockDim.x + threadIdx.x;
    if (i < Nn) {
        int o = g_offs[i] + g_bsum[i >> 8];
        g_offs[i] = o;
        g_cursor[i] = o;
    }
    if (i == 0) g_offs[Nn] = EN;
}

__global__ void fill_kernel(const int* __restrict__ ei, int E, int Nn) {
    int i = blockIdx.x * blockDim.x + threadIdx.x;
    if (i >= E + Nn) return;
    int src = i < E ? ei[i] : i - E;
    int dst = i < E ? ei[E + i] : i - E;
    int pos = atomicAdd(&g_cursor[dst], 1);
    g_csr[pos] = src;
}

__global__ void att1_kernel(const float* __restrict__ a_src,
                            const float* __restrict__ a_dst, int Nn) {
    int gw   = (blockIdx.x * blockDim.x + threadIdx.x) >> 5;
    int lane = threadIdx.x & 31;
    if (gw >= Nn) return;
    const float* row = g_h1 + (size_t)gw * HID2;
    float h0a = row[lane], h0b = row[lane + 32];
    float h1a = row[64 + lane], h1b = row[96 + lane];
    float s0 = h0a * a_src[lane] + h0b * a_src[lane + 32];
    float d0 = h0a * a_dst[lane] + h0b * a_dst[lane + 32];
    float s1 = h1a * a_src[64 + lane] + h1b * a_src[96 + lane];
    float d1 = h1a * a_dst[64 + lane] + h1b * a_dst[96 + lane];
#pragma unroll
    for (int o = 16; o; o >>= 1) {
        s0 += __shfl_down_sync(0xffffffffu, s0, o);
        d0 += __shfl_down_sync(0xffffffffu, d0, o);
        s1 += __shfl_down_sync(0xffffffffu, s1, o);
        d1 += __shfl_down_sync(0xffffffffu, d1, o);
    }
    if (lane == 0) {
        g_asrc1[gw * 2] = s0; g_asrc1[gw * 2 + 1] = s1;
        g_adst1[gw * 2] = d0; g_adst1[gw * 2 + 1] = d1;
    }
}

__global__ void att2_kernel(const float* __restrict__ a_src,
                            const float* __restrict__ a_dst, int Nn) {
    int gw   = (blockIdx.x * blockDim.x + threadIdx.x) >> 5;
    int lane = threadIdx.x & 31;
    if (gw >= Nn) return;
    const float* row = g_h2 + (size_t)gw * HH;
    float ha = row[lane], hb = row[lane + 32];
    float s = ha * a_src[lane] + hb * a_src[lane + 32];
    float d = ha * a_dst[lane] + hb * a_dst[lane + 32];
#pragma unroll
    for (int o = 16; o; o >>= 1) {
        s += __shfl_down_sync(0xffffffffu, s, o);
        d += __shfl_down_sync(0xffffffffu, d, o);
    }
    if (lane == 0) { g_asrc2[gw] = s; g_adst2[gw] = d; }
}

// gather1: softmax-weighted aggregation + fused elu(.+b1) epilogue
__global__ void gather1(const float* __restrict__ b1, int Nn) {
    int w    = (blockIdx.x * blockDim.x + threadIdx.x) >> 5;
    int lane = threadIdx.x & 31;
    if (w >= Nn) return;
    int s = g_offs[w], e = g_offs[w + 1];
    float2 ad = *(const float2*)&g_adst1[w * 2];
    float4 acc = make_float4(0.f, 0.f, 0.f, 0.f);
    float d0 = 0.f, d1 = 0.f;
    const float* h1base = g_h1 + lane * 4;
    for (int i = s; i < e; i++) {
        int src = __ldg(&g_csr[i]);
        float2 as = *(const float2*)&g_asrc1[src * 2];
        float e0 = __expf(lrelu(as.x + ad.x));
        float e1 = __expf(lrelu(as.y + ad.y));
        d0 += e0; d1 += e1;
        float al = (lane < 16) ? e0 : e1;
        float4 v = *(const float4*)(h1base + (size_t)src * HID2);
        acc.x += al * v.x; acc.y += al * v.y;
        acc.z += al * v.z; acc.w += al * v.w;
    }
    float rd = (lane < 16) ? (1.f / d0) : (1.f / d1);
    float4 bb = *(const float4*)(b1 + lane * 4);
    acc.x = eluf(acc.x * rd + bb.x);
    acc.y = eluf(acc.y * rd + bb.y);
    acc.z = eluf(acc.z * rd + bb.z);
    acc.w = eluf(acc.w * rd + bb.w);
    *(float4*)(g_out1 + (size_t)w * HID2 + lane * 4) = acc;
}

__global__ void gather2(int Nn) {
    int w    = (blockIdx.x * blockDim.x + threadIdx.x) >> 5;
    int lane = threadIdx.x & 31;
    if (w >= Nn) return;
    int s = g_offs[w], e = g_offs[w + 1];
    float ad = g_adst2[w];
    float2 acc = make_float2(0.f, 0.f);
    float d = 0.f;
    const float* h2base = g_h2 + lane * 2;
    for (int i = s; i < e; i++) {
        int src = __ldg(&g_csr[i]);
        float ee = __expf(lrelu(g_asrc2[src] + ad));
        d += ee;
        float2 v = *(const float2*)(h2base + (size_t)src * HH);
        acc.x += ee * v.x; acc.y += ee * v.y;
    }
    float rd = 1.f / d;
    acc.x *= rd; acc.y *= rd;
    *(float2*)(g_out2 + (size_t)w * HH + lane * 2) = acc;
}

__global__ void final_kernel(const float* __restrict__ b2,
                             const float* __restrict__ Wc1,
                             const float* __restrict__ bc1,
                             const float* __restrict__ Wc2,
                             const float* __restrict__ bc2,
                             float* __restrict__ out, int Nn) {
    __shared__ float sW1[64 * 16], sW2[32], sb1[16], sb2[2], sB2[64];
    int tid = threadIdx.x;
    for (int i = tid; i < 64 * 16; i += blockDim.x) sW1[i] = Wc1[i];
    if (tid < 32) sW2[tid] = Wc2[tid];
    if (tid < 16) sb1[tid] = bc1[tid];
    if (tid < 2)  sb2[tid] = bc2[tid];
    if (tid < 64) sB2[tid] = b2[tid];
    __syncthreads();
    int n = blockIdx.x * blockDim.x + tid;
    if (n >= Nn) return;
    const float* row = g_out2 + (size_t)n * HH;
    float t[16];
#pragma unroll
    for (int j = 0; j < 16; j++) t[j] = sb1[j];
#pragma unroll 8
    for (int i = 0; i < 64; i++) {
        float v = row[i] + sB2[i];
#pragma unroll
        for (int j = 0; j < 16; j++) t[j] += v * sW1[i * 16 + j];
    }
    float o0 = sb2[0], o1 = sb2[1];
#pragma unroll
    for (int j = 0; j < 16; j++) {
        float tj = t[j] > 0.f ? t[j] : 0.f;
        o0 += tj * sW2[j * 2]; o1 += tj * sW2[j * 2 + 1];
    }
    out[n * 2]     = o0;
    out[n * 2 + 1] = o1;
}

extern "C" void kernel_launch(void* const* d_in, const int* in_sizes, int n_in,
                              void* d_out, int out_size) {
    const float* x  = (const float*)d_in[0];
    const int*   ei = (const int*)d_in[1];
    int Nn = in_sizes[0] / FIN;
    int E  = in_sizes[1] / 2;

    int g = -1;
    for (int i = 2; i + 2 < n_in; i++) {
        if (in_sizes[i] == 256 && in_sizes[i + 1] == 256 && in_sizes[i + 2] == FIN * HID2) {
            g = i; break;
        }
    }
    if (g < 0) g = 6;
    const float* gamma  = (const float*)d_in[g + 0];
    const float* beta   = (const float*)d_in[g + 1];
    const float* W1     = (const float*)d_in[g + 2];
    const float* a_src1 = (const float*)d_in[g + 3];
    const float* a_dst1 = (const float*)d_in[g + 4];
    const float* b1     = (const float*)d_in[g + 5];
    const float* W2     = (const float*)d_in[g + 6];
    const float* a_src2 = (const float*)d_in[g + 7];
    const float* a_dst2 = (const float*)d_in[g + 8];
    const float* b2     = (const float*)d_in[g + 9];
    const float* Wc1    = (const float*)d_in[g + 10];
    const float* bc1    = (const float*)d_in[g + 11];
    const float* Wc2    = (const float*)d_in[g + 12];
    const float* bc2    = (const float*)d_in[g + 13];
    float* out = (float*)d_out;

    float *p_h1, *p_out1, *p_h2, *p_W1p, *p_c1;
    cudaGetSymbolAddress((void**)&p_h1,   g_h1);
    cudaGetSymbolAddress((void**)&p_out1, g_out1);
    cudaGetSymbolAddress((void**)&p_h2,   g_h2);
    cudaGetSymbolAddress((void**)&p_W1p,  g_W1p);
    cudaGetSymbolAddress((void**)&p_c1,   g_c1);

    int EN = E + Nn;
    int nScanBlocks = (Nn + 255) / 256;

    init_kernel<<<(Nn + 255) / 256, 256>>>(Nn);

    int rowsPerBlock = 256;
    int nStatBlocks = (Nn + rowsPerBlock - 1) / rowsPerBlock;
    stats_kernel<<<nStatBlocks, 256>>>(x, gamma, beta, Nn, rowsPerBlock, nStatBlocks);

    prep_w1c1<<<129, 256>>>(W1);

    // GEMM1: h1 = xn @ W1 (BN folded), 3xTF32 tensor cores
    gemm_tc<128, 128, 16>
        <<<(Nn + 127) / 128, 256>>>(Nn, HID2, FIN, x, p_W1p, p_c1, p_h1);

    hist_kernel<<<(EN + 255) / 256, 256>>>(ei, E, Nn);
    scanA<<<nScanBlocks, 256>>>(Nn);
    scanB<<<1, 256>>>(nScanBlocks);
    scanC<<<(Nn + 255) / 256, 256>>>(Nn, EN);
    fill_kernel<<<(EN + 255) / 256, 256>>>(ei, E, Nn);

    att1_kernel<<<(Nn * 32 + 255) / 256, 256>>>(a_src1, a_dst1, Nn);
    gather1<<<((size_t)Nn * 32 + 255) / 256, 256>>>(b1, Nn);

    // GEMM2: h2 = out1 @ W2 (A already elu(.+b1)-activated), 3xTF32
    gemm_tc<128, 64, 16>
        <<<(Nn + 127) / 128, 256>>>(Nn, HH, HID2, p_out1, W2, nullptr, p_h2);

    att2_kernel<<<(Nn * 32 + 255) / 256, 256>>>(a_src2, a_dst2, Nn);
    gather2<<<((size_t)Nn * 32 + 255) / 256, 256>>>(Nn);

    final_kernel<<<(Nn + 255) / 256, 256>>>(b2, Wc1, bc1, Wc2, bc2, out, Nn);
}